// round 1
// baseline (speedup 1.0000x reference)
#include <cuda_runtime.h>

// ---------------------------------------------------------------------------
// QuantSoftmax (I-BERT int softmax) for x: (2,12,1024,1024) fp32, row = 1024.
//
// Pass 1: global abs-max  -> per-block partials (fixed 1024 slots)
// Pass 1b: reduce partials, derive ALL loop-invariant scalars (scale, x0_int,
//          b_int, c_int, exp_sf, scale2 [analytic!], reciprocals)
// Pass 2: one block per row: quantize, row-max, int-exp poly, requant,
//          exact row sum (int + Sterbenz residual, combined in fp64),
//          factor, floor-quantize output.
// Tail:    fill trailing out elements with out_scale = 1/256.
// ---------------------------------------------------------------------------

#define ROWLEN 1024
#define K1_BLOCKS 1024
#define K1_THREADS 256

static __device__ float g_part[K1_BLOCKS];

struct QParams {
    float s;       // scaling_factor
    float ys;      // rn(1/s)
    float x0i;     // floor(-0.6931 / s)
    float yx0;     // rn(1/x0i)
    float bi;      // floor(COEF_B / s)
    float ci;      // floor(COEF_C / s^2)
    float exp_sf;  // (COEF_A * s^2) / 2^30
    float scale2;  // inner QuantAct scale (analytic global max of exp_real)
    float ys2;     // rn(1/scale2)
    float t30x0;   // 30 * x0i
};
static __device__ QParams g_p;

// Correctly-rounded a/b given y = __frcp_rn(b)  (Markstein refinement).
__device__ __forceinline__ float fdivrn(float a, float b, float y) {
    float q0 = __fmul_rn(a, y);
    float r0 = __fmaf_rn(-b, q0, a);
    return __fmaf_rn(r0, y, q0);
}

// ---------------- Pass 1: per-block abs-max partials -----------------------
__global__ void __launch_bounds__(K1_THREADS) k_absmax(const float4* __restrict__ x, int n4) {
    float m = 0.0f;
    int stride = gridDim.x * blockDim.x;
    for (int i = blockIdx.x * blockDim.x + threadIdx.x; i < n4; i += stride) {
        float4 v = x[i];
        m = fmaxf(m, fmaxf(fmaxf(fabsf(v.x), fabsf(v.y)),
                           fmaxf(fabsf(v.z), fabsf(v.w))));
    }
#pragma unroll
    for (int o = 16; o > 0; o >>= 1)
        m = fmaxf(m, __shfl_xor_sync(0xffffffffu, m, o));
    __shared__ float sm[K1_THREADS / 32];
    if ((threadIdx.x & 31) == 0) sm[threadIdx.x >> 5] = m;
    __syncthreads();
    if (threadIdx.x == 0) {
#pragma unroll
        for (int i = 1; i < K1_THREADS / 32; i++) m = fmaxf(m, sm[i]);
        g_part[blockIdx.x] = m;
    }
}

// ---------------- Pass 1b: finish reduction + derive scalars ---------------
__global__ void __launch_bounds__(1024) k_params() {
    float m = g_part[threadIdx.x];
#pragma unroll
    for (int o = 16; o > 0; o >>= 1)
        m = fmaxf(m, __shfl_xor_sync(0xffffffffu, m, o));
    __shared__ float sm[32];
    if ((threadIdx.x & 31) == 0) sm[threadIdx.x >> 5] = m;
    __syncthreads();
    if (threadIdx.x == 0) {
#pragma unroll
        for (int i = 1; i < 32; i++) m = fmaxf(m, sm[i]);

        // Constants exactly as the python reference materializes them in fp32.
        const float CA  = (float)(0.35815147);
        const float CB  = (float)(0.96963238 / 0.35815147);
        const float CC  = (float)(1.0 / 0.35815147);
        const float X0F = (float)(-0.6931);

        float s   = __fdiv_rn(m, 32767.0f);
        float x0i = floorf(__fdiv_rn(X0F, s));
        float bi  = floorf(__fdiv_rn(CB, s));
        float s2  = __fmul_rn(s, s);
        float ci  = floorf(__fdiv_rn(CC, s2));
        // exp_sf = fl(CA*s2) / 2^30  (divide by power of two is exact)
        float exp_sf = __fmul_rn(__fmul_rn(CA, s2), 9.31322574615478516e-10f /* 2^-30 */);
        // Global max of exp_real is attained at every row max:
        //   exp_int = floor(ci * 2^30) = ci * 2^30 (exact),  er = fl(exp_int * exp_sf)
        float ermax  = __fmul_rn(__fmul_rn(ci, 1073741824.0f), exp_sf);
        float scale2 = __fdiv_rn(ermax, 32767.0f);

        QParams p;
        p.s = s;          p.ys  = __frcp_rn(s);
        p.x0i = x0i;      p.yx0 = __frcp_rn(x0i);
        p.bi = bi;        p.ci  = ci;
        p.exp_sf = exp_sf;
        p.scale2 = scale2; p.ys2 = __frcp_rn(scale2);
        p.t30x0 = __fmul_rn(30.0f, x0i);
        g_p = p;
    }
}

// ---------------- Pass 2: per-row int softmax -------------------------------
__global__ void __launch_bounds__(256) k_softmax(const float* __restrict__ x,
                                                 float* __restrict__ out) {
    __shared__ float s_f[8];
    __shared__ int   s_i[8];
    __shared__ float s_b[2];

    const QParams p = g_p;

    size_t row = blockIdx.x;
    const float4* xr = reinterpret_cast<const float4*>(x + row * ROWLEN);
    float4 v = xr[threadIdx.x];
    float xa[4] = {v.x, v.y, v.z, v.w};

    // --- quantize + dequantized integer representation, local max ---
    float xii[4];
    float lmax = -3.0e38f;
#pragma unroll
    for (int j = 0; j < 4; j++) {
        float xi = rintf(fdivrn(xa[j], p.s, p.ys));
        xi = fminf(fmaxf(xi, -32768.0f), 32767.0f);
        float qx = __fmul_rn(xi, p.s);
        xii[j] = fdivrn(qx, p.s, p.ys);
        lmax = fmaxf(lmax, xii[j]);
    }

    // --- block max -> rmax ---
#pragma unroll
    for (int o = 16; o > 0; o >>= 1)
        lmax = fmaxf(lmax, __shfl_xor_sync(0xffffffffu, lmax, o));
    if ((threadIdx.x & 31) == 0) s_f[threadIdx.x >> 5] = lmax;
    __syncthreads();
    if (threadIdx.x == 0) {
        float m = s_f[0];
#pragma unroll
        for (int i = 1; i < 8; i++) m = fmaxf(m, s_f[i]);
        s_b[0] = m;
    }
    __syncthreads();
    float rmax = s_b[0];

    // --- int exp + inner requant; accumulate exact sum (int + residual) ---
    float e2[4];
    int   ksum = 0;
    float dsum = 0.0f;
#pragma unroll
    for (int j = 0; j < 4; j++) {
        float t = __fsub_rn(xii[j], rmax);
        t = fmaxf(t, p.t30x0);
        float q = floorf(fdivrn(t, p.x0i, p.yx0));
        float r = __fsub_rn(t, __fmul_rn(p.x0i, q));
        float z = __fadd_rn(__fmul_rn(r, __fadd_rn(r, p.bi)), p.ci);
        // 2^(30-q): q integer-valued in [0,30] -> exact bit construction
        int e = (int)__fsub_rn(30.0f, q);
        float p2 = __int_as_float((e + 127) << 23);
        float ei = fmaxf(floorf(__fmul_rn(z, p2)), 0.0f);
        float er = __fmul_rn(ei, p.exp_sf);
        float kf = rintf(fdivrn(er, p.scale2, p.ys2));
        kf = fminf(fmaxf(kf, -32768.0f), 32767.0f);
        float erq = __fmul_rn(kf, p.scale2);
        float ee = fdivrn(erq, p.scale2, p.ys2);
        e2[j] = ee;
        ksum += (int)kf;
        dsum = __fadd_rn(dsum, __fsub_rn(ee, kf));  // Sterbenz: exact residual
    }

    // --- block sum (int + float residual) ---
#pragma unroll
    for (int o = 16; o > 0; o >>= 1) {
        ksum += __shfl_xor_sync(0xffffffffu, ksum, o);
        dsum = __fadd_rn(dsum, __shfl_xor_sync(0xffffffffu, dsum, o));
    }
    if ((threadIdx.x & 31) == 0) {
        s_i[threadIdx.x >> 5] = ksum;
        s_f[threadIdx.x >> 5] = dsum;
    }
    __syncthreads();
    if (threadIdx.x == 0) {
        int   K = s_i[0];
        float D = s_f[0];
#pragma unroll
        for (int i = 1; i < 8; i++) { K += s_i[i]; D = __fadd_rn(D, s_f[i]); }
        float sumf = (float)((double)K + (double)D);  // correctly-rounded row sum
        s_b[1] = floorf(__fdiv_rn(4294967296.0f, sumf));
    }
    __syncthreads();
    float factor = s_b[1];

    // --- output: floor(e2 * factor / 2^24) * (1/256) ---
    float4 o;
    float ov[4];
#pragma unroll
    for (int j = 0; j < 4; j++) {
        float t1 = __fmul_rn(e2[j], factor);
        float t2 = __fmul_rn(t1, 5.96046447753906250e-08f /* 2^-24, exact */);
        ov[j] = __fmul_rn(floorf(t2), 0.00390625f /* 1/256, exact */);
    }
    o.x = ov[0]; o.y = ov[1]; o.z = ov[2]; o.w = ov[3];
    reinterpret_cast<float4*>(out)[row * (ROWLEN / 4) + threadIdx.x] = o;
}

// ---------------- tail: out_scale scalar(s) ---------------------------------
__global__ void k_tail(float* __restrict__ out, int start, int total) {
    int i = start + blockIdx.x * blockDim.x + threadIdx.x;
    if (i < total) out[i] = 0.00390625f;  // 1/2^8
}

extern "C" void kernel_launch(void* const* d_in, const int* in_sizes, int n_in,
                              void* d_out, int out_size) {
    const float* x = (const float*)d_in[0];
    float* out = (float*)d_out;
    int n = in_sizes[0];
    int n4 = n / 4;

    k_absmax<<<K1_BLOCKS, K1_THREADS>>>((const float4*)x, n4);
    k_params<<<1, 1024>>>();

    int rows = n / ROWLEN;
    k_softmax<<<rows, 256>>>(x, out);

    if (out_size > n) {
        int tail = out_size - n;
        k_tail<<<(tail + 255) / 256, 256>>>(out, n, out_size);
    }
}

// round 2
// speedup vs baseline: 1.0503x; 1.0503x over previous
#include <cuda_runtime.h>

// ---------------------------------------------------------------------------
// QuantSoftmax (I-BERT int softmax) for x: (2,12,1024,1024) fp32, row = 1024.
//
// Pass 1: global abs-max  -> per-block partials (fixed 1024 slots)
// Pass 1b: reduce partials, derive loop-invariant scalars, write out_scale tail
// Pass 2: one block per row; output via streaming stores (__stcs) so the
//         input stays resident in L2 between pass1 and pass2.
// ---------------------------------------------------------------------------

#define ROWLEN 1024
#define K1_BLOCKS 1024
#define K1_THREADS 256

static __device__ float g_part[K1_BLOCKS];

struct QParams {
    float s;       // scaling_factor
    float ys;      // rn(1/s)
    float x0i;     // floor(-0.6931 / s)
    float yx0;     // rn(1/x0i)
    float bi;      // floor(COEF_B / s)
    float ci;      // floor(COEF_C / s^2)
    float exp_sf;  // (COEF_A * s^2) / 2^30
    float scale2;  // inner QuantAct scale (analytic global max of exp_real)
    float ys2;     // rn(1/scale2)
    float t30x0;   // 30 * x0i
};
static __device__ QParams g_p;

// Correctly-rounded a/b given y = __frcp_rn(b)  (Markstein refinement).
__device__ __forceinline__ float fdivrn(float a, float b, float y) {
    float q0 = __fmul_rn(a, y);
    float r0 = __fmaf_rn(-b, q0, a);
    return __fmaf_rn(r0, y, q0);
}

// ---------------- Pass 1: per-block abs-max partials -----------------------
__global__ void __launch_bounds__(K1_THREADS) k_absmax(const float4* __restrict__ x, int n4) {
    float m = 0.0f;
    int stride = gridDim.x * blockDim.x;
    for (int i = blockIdx.x * blockDim.x + threadIdx.x; i < n4; i += stride) {
        float4 v = x[i];
        m = fmaxf(m, fmaxf(fmaxf(fabsf(v.x), fabsf(v.y)),
                           fmaxf(fabsf(v.z), fabsf(v.w))));
    }
#pragma unroll
    for (int o = 16; o > 0; o >>= 1)
        m = fmaxf(m, __shfl_xor_sync(0xffffffffu, m, o));
    __shared__ float sm[K1_THREADS / 32];
    if ((threadIdx.x & 31) == 0) sm[threadIdx.x >> 5] = m;
    __syncthreads();
    if (threadIdx.x == 0) {
#pragma unroll
        for (int i = 1; i < K1_THREADS / 32; i++) m = fmaxf(m, sm[i]);
        g_part[blockIdx.x] = m;
    }
}

// ---------------- Pass 1b: finish reduction + derive scalars + tail --------
__global__ void __launch_bounds__(1024) k_params(float* __restrict__ out,
                                                 int n, int out_size) {
    // out_scale tail elements (usually 1 scalar)
    for (int i = n + threadIdx.x; i < out_size; i += 1024)
        out[i] = 0.00390625f;  // 1 / 2^8

    float m = g_part[threadIdx.x];
#pragma unroll
    for (int o = 16; o > 0; o >>= 1)
        m = fmaxf(m, __shfl_xor_sync(0xffffffffu, m, o));
    __shared__ float sm[32];
    if ((threadIdx.x & 31) == 0) sm[threadIdx.x >> 5] = m;
    __syncthreads();
    if (threadIdx.x == 0) {
#pragma unroll
        for (int i = 1; i < 32; i++) m = fmaxf(m, sm[i]);

        const float CA  = (float)(0.35815147);
        const float CB  = (float)(0.96963238 / 0.35815147);
        const float CC  = (float)(1.0 / 0.35815147);
        const float X0F = (float)(-0.6931);

        float s   = __fdiv_rn(m, 32767.0f);
        float x0i = floorf(__fdiv_rn(X0F, s));
        float bi  = floorf(__fdiv_rn(CB, s));
        float s2  = __fmul_rn(s, s);
        float ci  = floorf(__fdiv_rn(CC, s2));
        float exp_sf = __fmul_rn(__fmul_rn(CA, s2), 9.31322574615478516e-10f /* 2^-30 */);
        // Global max of exp_real (attained at every row max):
        float ermax  = __fmul_rn(__fmul_rn(ci, 1073741824.0f), exp_sf);
        float scale2 = __fdiv_rn(ermax, 32767.0f);

        QParams p;
        p.s = s;          p.ys  = __frcp_rn(s);
        p.x0i = x0i;      p.yx0 = __frcp_rn(x0i);
        p.bi = bi;        p.ci  = ci;
        p.exp_sf = exp_sf;
        p.scale2 = scale2; p.ys2 = __frcp_rn(scale2);
        p.t30x0 = __fmul_rn(30.0f, x0i);
        g_p = p;
    }
}

// ---------------- Pass 2: per-row int softmax -------------------------------
__global__ void __launch_bounds__(256) k_softmax(const float* __restrict__ x,
                                                 float* __restrict__ out) {
    __shared__ float s_max[8];
    __shared__ int   s_i[8];
    __shared__ float s_d[8];
    __shared__ float s_f24;

    const QParams p = g_p;

    size_t row = blockIdx.x;
    const float4* xr = reinterpret_cast<const float4*>(x + row * ROWLEN);
    float4 v = xr[threadIdx.x];
    float xa[4] = {v.x, v.y, v.z, v.w};

    // --- quantize + dequantized integer representation, local max ---
    // Clamps are provably dead: |x| <= max|x|  =>  |x/s| <= 32767*(1+2^-23) < 32767.5
    float xii[4];
    float lmax = -3.0e38f;
#pragma unroll
    for (int j = 0; j < 4; j++) {
        float xi = rintf(fdivrn(xa[j], p.s, p.ys));
        float qx = __fmul_rn(xi, p.s);
        xii[j] = fdivrn(qx, p.s, p.ys);
        lmax = fmaxf(lmax, xii[j]);
    }

    // --- block max (single barrier; every thread folds the 8 partials) ---
#pragma unroll
    for (int o = 16; o > 0; o >>= 1)
        lmax = fmaxf(lmax, __shfl_xor_sync(0xffffffffu, lmax, o));
    if ((threadIdx.x & 31) == 0) s_max[threadIdx.x >> 5] = lmax;
    __syncthreads();
    float rmax = s_max[0];
#pragma unroll
    for (int i = 1; i < 8; i++) rmax = fmaxf(rmax, s_max[i]);

    // --- int exp + inner requant; exact row sum (int + Sterbenz residual) ---
    float e2[4];
    int   ksum = 0;
    float dsum = 0.0f;
#pragma unroll
    for (int j = 0; j < 4; j++) {
        float t = __fsub_rn(xii[j], rmax);
        t = fmaxf(t, p.t30x0);
        float q = floorf(fdivrn(t, p.x0i, p.yx0));
        float r = __fsub_rn(t, __fmul_rn(p.x0i, q));
        float z = __fadd_rn(__fmul_rn(r, __fadd_rn(r, p.bi)), p.ci);
        // 2^(30-q): q integer-valued in [0,30] -> exact bit construction
        int e = (int)__fsub_rn(30.0f, q);
        float p2 = __int_as_float((e + 127) << 23);
        float ei = fmaxf(floorf(__fmul_rn(z, p2)), 0.0f);
        float er = __fmul_rn(ei, p.exp_sf);
        // kf in [0, 32767]: clamp dead (er <= ermax, scale2 = ermax/32767)
        float kf = rintf(fdivrn(er, p.scale2, p.ys2));
        float erq = __fmul_rn(kf, p.scale2);
        float ee = fdivrn(erq, p.scale2, p.ys2);
        e2[j] = ee;
        ksum += (int)kf;
        dsum = __fadd_rn(dsum, __fsub_rn(ee, kf));  // exact residual (Sterbenz)
    }

    // --- block sum: redux for int, shfl for fp residual ---
    ksum = __reduce_add_sync(0xffffffffu, ksum);
#pragma unroll
    for (int o = 16; o > 0; o >>= 1)
        dsum = __fadd_rn(dsum, __shfl_xor_sync(0xffffffffu, dsum, o));
    if ((threadIdx.x & 31) == 0) {
        s_i[threadIdx.x >> 5] = ksum;
        s_d[threadIdx.x >> 5] = dsum;
    }
    __syncthreads();
    if (threadIdx.x == 0) {
        int   K = s_i[0];
        float D = s_d[0];
#pragma unroll
        for (int i = 1; i < 8; i++) { K += s_i[i]; D = __fadd_rn(D, s_d[i]); }
        float sumf = (float)((double)K + (double)D);  // correctly-rounded row sum
        float factor = floorf(__fdiv_rn(4294967296.0f, sumf));
        // factor * 2^-24: exact power-of-2 scale, commutes with fp32 rounding
        s_f24 = __fmul_rn(factor, 5.96046447753906250e-08f);
    }
    __syncthreads();
    float f24 = s_f24;

    // --- output: floor(e2 * factor / 2^24) * (1/256), streaming store ---
    float4 o;
    float ov[4];
#pragma unroll
    for (int j = 0; j < 4; j++) {
        float t2 = __fmul_rn(e2[j], f24);
        ov[j] = __fmul_rn(floorf(t2), 0.00390625f /* 1/256 */);
    }
    o.x = ov[0]; o.y = ov[1]; o.z = ov[2]; o.w = ov[3];
    // evict-first store: don't let the output evict x from L2
    __stcs(reinterpret_cast<float4*>(out) + row * (ROWLEN / 4) + threadIdx.x, o);
}

extern "C" void kernel_launch(void* const* d_in, const int* in_sizes, int n_in,
                              void* d_out, int out_size) {
    const float* x = (const float*)d_in[0];
    float* out = (float*)d_out;
    int n = in_sizes[0];
    int n4 = n / 4;

    k_absmax<<<K1_BLOCKS, K1_THREADS>>>((const float4*)x, n4);
    k_params<<<1, 1024>>>(out, n, out_size);

    int rows = n / ROWLEN;
    k_softmax<<<rows, 256>>>(x, out);
}

// round 3
// speedup vs baseline: 1.0778x; 1.0262x over previous
#include <cuda_runtime.h>

// ---------------------------------------------------------------------------
// QuantSoftmax (I-BERT int softmax) for x: (2,12,1024,1024) fp32, row = 1024.
//
// Kernel 1: global abs-max (grid partials + last-block-finishes reduction),
//           derives all loop-invariant scalars, writes out_scale tail.
// Kernel 2: WARP-per-row int softmax. 32 elems/lane in registers, shfl-only
//           reductions, no __syncthreads, no smem. Streaming output stores.
// ---------------------------------------------------------------------------

#define ROWLEN 1024
#define K1_BLOCKS 1024
#define K1_THREADS 256

static __device__ float g_part[K1_BLOCKS];
static __device__ unsigned g_count = 0;

struct QParams {
    float s;       // scaling_factor
    float ys;      // rn(1/s)
    float x0i;     // floor(-0.6931 / s)
    float yx0;     // rn(1/x0i)
    float bi;      // floor(COEF_B / s)
    float ci;      // floor(COEF_C / s^2)
    float exp_sf;  // (COEF_A * s^2) / 2^30
    float scale2;  // inner QuantAct scale (analytic global max of exp_real)
    float ys2;     // rn(1/scale2)
    float t30x0;   // 30 * x0i
};
static __device__ QParams g_p;

// Correctly-rounded a/b given y = __frcp_rn(b)  (Markstein refinement).
__device__ __forceinline__ float fdivrn(float a, float b, float y) {
    float q0 = __fmul_rn(a, y);
    float r0 = __fmaf_rn(-b, q0, a);
    return __fmaf_rn(r0, y, q0);
}

// ------------- Kernel 1: abs-max + params + tail (single kernel) -----------
__global__ void __launch_bounds__(K1_THREADS) k_absmax(const float4* __restrict__ x, int n4,
                                                       float* __restrict__ out,
                                                       int n, int out_size) {
    float m = 0.0f;
    int stride = gridDim.x * blockDim.x;
    for (int i = blockIdx.x * blockDim.x + threadIdx.x; i < n4; i += stride) {
        float4 v = x[i];
        m = fmaxf(m, fmaxf(fmaxf(fabsf(v.x), fabsf(v.y)),
                           fmaxf(fabsf(v.z), fabsf(v.w))));
    }
#pragma unroll
    for (int o = 16; o > 0; o >>= 1)
        m = fmaxf(m, __shfl_xor_sync(0xffffffffu, m, o));
    __shared__ float sm[K1_THREADS / 32];
    __shared__ bool amLast;
    if ((threadIdx.x & 31) == 0) sm[threadIdx.x >> 5] = m;
    __syncthreads();
    if (threadIdx.x == 0) {
#pragma unroll
        for (int i = 1; i < K1_THREADS / 32; i++) m = fmaxf(m, sm[i]);
        g_part[blockIdx.x] = m;
        __threadfence();
        unsigned prev = atomicAdd(&g_count, 1u);
        amLast = (prev == gridDim.x - 1);
    }
    __syncthreads();
    if (!amLast) return;

    // ---- last block: finish reduction over 1024 partials ----
    float mm = 0.0f;
#pragma unroll
    for (int k = 0; k < K1_BLOCKS / K1_THREADS; k++)
        mm = fmaxf(mm, __ldcg(&g_part[threadIdx.x + k * K1_THREADS]));
#pragma unroll
    for (int o = 16; o > 0; o >>= 1)
        mm = fmaxf(mm, __shfl_xor_sync(0xffffffffu, mm, o));
    if ((threadIdx.x & 31) == 0) sm[threadIdx.x >> 5] = mm;
    __syncthreads();

    // out_scale tail elements (usually 1 scalar)
    for (int i = n + threadIdx.x; i < out_size; i += K1_THREADS)
        out[i] = 0.00390625f;  // 1 / 2^8

    if (threadIdx.x == 0) {
        mm = sm[0];
#pragma unroll
        for (int i = 1; i < K1_THREADS / 32; i++) mm = fmaxf(mm, sm[i]);

        const float CA  = (float)(0.35815147);
        const float CB  = (float)(0.96963238 / 0.35815147);
        const float CC  = (float)(1.0 / 0.35815147);
        const float X0F = (float)(-0.6931);

        float s   = __fdiv_rn(mm, 32767.0f);
        float x0i = floorf(__fdiv_rn(X0F, s));
        float bi  = floorf(__fdiv_rn(CB, s));
        float s2  = __fmul_rn(s, s);
        float ci  = floorf(__fdiv_rn(CC, s2));
        float exp_sf = __fmul_rn(__fmul_rn(CA, s2), 9.31322574615478516e-10f /* 2^-30 */);
        // Global max of exp_real (attained at every row max):
        float ermax  = __fmul_rn(__fmul_rn(ci, 1073741824.0f), exp_sf);
        float scale2 = __fdiv_rn(ermax, 32767.0f);

        QParams p;
        p.s = s;          p.ys  = __frcp_rn(s);
        p.x0i = x0i;      p.yx0 = __frcp_rn(x0i);
        p.bi = bi;        p.ci  = ci;
        p.exp_sf = exp_sf;
        p.scale2 = scale2; p.ys2 = __frcp_rn(scale2);
        p.t30x0 = __fmul_rn(30.0f, x0i);
        g_p = p;
        g_count = 0;  // reset for next graph replay
    }
}

// ------------- Kernel 2: warp-per-row int softmax ---------------------------
__global__ void __launch_bounds__(256, 2) k_softmax(const float* __restrict__ x,
                                                    float* __restrict__ out) {
    const QParams p = g_p;

    const unsigned lane = threadIdx.x & 31u;
    const size_t row = ((size_t)blockIdx.x * blockDim.x + threadIdx.x) >> 5;

    const float4* xr = reinterpret_cast<const float4*>(x + row * ROWLEN);
    float4* orow = reinterpret_cast<float4*>(out + row * ROWLEN);

    // --- load full row: 8 float4 per lane, coalesced (chunk-major) ---
    float4 v[8];
#pragma unroll
    for (int k = 0; k < 8; k++) v[k] = xr[k * 32 + lane];

    // --- quantize + dequantized integer representation; local max ---
    // Clamps are provably dead: |x| <= max|x| => |x/s| <= 32767*(1+2^-23) < 32767.5
    float pay[32];
    float lmax = -3.0e38f;
#pragma unroll
    for (int k = 0; k < 8; k++) {
        float e[4] = {v[k].x, v[k].y, v[k].z, v[k].w};
#pragma unroll
        for (int j = 0; j < 4; j++) {
            float xi = rintf(fdivrn(e[j], p.s, p.ys));
            float qx = __fmul_rn(xi, p.s);
            float xii = fdivrn(qx, p.s, p.ys);
            pay[k * 4 + j] = xii;
            lmax = fmaxf(lmax, xii);
        }
    }

    // --- row max: warp shuffle only ---
#pragma unroll
    for (int o = 16; o > 0; o >>= 1)
        lmax = fmaxf(lmax, __shfl_xor_sync(0xffffffffu, lmax, o));
    const float rmax = lmax;

    // --- int exp + inner requant (in-place); exact sum (int + residual) ---
    int   ksum = 0;
    float dsum = 0.0f;
#pragma unroll
    for (int i = 0; i < 32; i++) {
        float t = __fsub_rn(pay[i], rmax);
        t = fmaxf(t, p.t30x0);
        float q = floorf(fdivrn(t, p.x0i, p.yx0));
        float r = __fsub_rn(t, __fmul_rn(p.x0i, q));
        float z = __fadd_rn(__fmul_rn(r, __fadd_rn(r, p.bi)), p.ci);
        // 2^(30-q): q integer-valued in [0,30] -> exact bit construction
        int e = (int)__fsub_rn(30.0f, q);
        float p2 = __int_as_float((e + 127) << 23);
        float ei = fmaxf(floorf(__fmul_rn(z, p2)), 0.0f);
        float er = __fmul_rn(ei, p.exp_sf);
        // kf in [0, 32767]: clamp dead (er <= ermax, scale2 = ermax/32767)
        float kf = rintf(fdivrn(er, p.scale2, p.ys2));
        float erq = __fmul_rn(kf, p.scale2);
        float ee = fdivrn(erq, p.scale2, p.ys2);
        pay[i] = ee;
        ksum += (int)kf;
        dsum = __fadd_rn(dsum, __fsub_rn(ee, kf));  // exact residual (Sterbenz)
    }

    // --- row sum: warp-level only ---
    ksum = __reduce_add_sync(0xffffffffu, ksum);
#pragma unroll
    for (int o = 16; o > 0; o >>= 1)
        dsum = __fadd_rn(dsum, __shfl_xor_sync(0xffffffffu, dsum, o));

    // every lane computes factor (one warp-instruction either way)
    float sumf = (float)((double)ksum + (double)dsum);  // correctly-rounded row sum
    float ysf = __frcp_rn(sumf);
    float factor = floorf(fdivrn(4294967296.0f, sumf, ysf));
    // factor * 2^-24: exact power-of-2 scale, commutes with fp32 rounding
    float f24 = __fmul_rn(factor, 5.96046447753906250e-08f);

    // --- output: floor(e2 * factor / 2^24) * (1/256), streaming stores ---
#pragma unroll
    for (int k = 0; k < 8; k++) {
        float4 o;
        o.x = __fmul_rn(floorf(__fmul_rn(pay[k * 4 + 0], f24)), 0.00390625f);
        o.y = __fmul_rn(floorf(__fmul_rn(pay[k * 4 + 1], f24)), 0.00390625f);
        o.z = __fmul_rn(floorf(__fmul_rn(pay[k * 4 + 2], f24)), 0.00390625f);
        o.w = __fmul_rn(floorf(__fmul_rn(pay[k * 4 + 3], f24)), 0.00390625f);
        __stcs(orow + k * 32 + lane, o);
    }
}

extern "C" void kernel_launch(void* const* d_in, const int* in_sizes, int n_in,
                              void* d_out, int out_size) {
    const float* x = (const float*)d_in[0];
    float* out = (float*)d_out;
    int n = in_sizes[0];
    int n4 = n / 4;

    k_absmax<<<K1_BLOCKS, K1_THREADS>>>((const float4*)x, n4, out, n, out_size);

    int rows = n / ROWLEN;           // 24576 rows, 8 warp-rows per block
    k_softmax<<<rows / 8, 256>>>(x, out);
}